// round 5
// baseline (speedup 1.0000x reference)
#include <cuda_runtime.h>

#define BN   4
#define CIN  64
#define COUT 64
#define HH   128
#define WW   128
#define HW   (HH * WW)
#define K2   9
#define OFFC (2 * K2)   // 18 offset channels

// Scratch for the intermediate offset field (no cudaMalloc allowed).
__device__ float g_offset[BN * OFFC * HW];

// ---------------------------------------------------------------------------
// Kernel 1: plain 3x3 conv, CIN=64 -> 18 offset channels, pad=1, stride=1.
// One thread = one pixel, 18 accumulators in registers. Full weights in smem,
// transposed so the inner co-loop reads contiguous floats (broadcast LDS).
// ---------------------------------------------------------------------------
__global__ __launch_bounds__(256, 1)
void offset_conv_kernel(const float* __restrict__ x,
                        const float* __restrict__ w,     // [18][64][3][3]
                        const float* __restrict__ bias)  // [18]
{
    __shared__ float ws[CIN * K2 * OFFC];  // [cq][co], 41472 B
    const int tid = threadIdx.x;
    for (int i = tid; i < CIN * K2 * OFFC; i += 256) {
        int cq = i / OFFC, co = i - cq * OFFC;
        ws[i] = w[co * (CIN * K2) + cq];
    }
    __syncthreads();

    const int pix = blockIdx.x * 256 + tid;          // 0 .. 65535
    const int b   = pix >> 14;
    const int hw  = pix & (HW - 1);
    const int ho  = hw >> 7;
    const int wo  = hw & (WW - 1);

    const float* xb = x + (size_t)b * CIN * HW;

    float acc[OFFC];
#pragma unroll
    for (int co = 0; co < OFFC; co++) acc[co] = bias[co];

    for (int c = 0; c < CIN; c++) {
        const float* xc = xb + c * HW;
#pragma unroll
        for (int kh = 0; kh < 3; kh++) {
            int y = ho - 1 + kh;
            if ((unsigned)y >= (unsigned)HH) continue;
#pragma unroll
            for (int kw = 0; kw < 3; kw++) {
                int xx = wo - 1 + kw;
                if ((unsigned)xx >= (unsigned)WW) continue;
                float v = __ldg(xc + y * WW + xx);
                const float* wr = &ws[(c * K2 + kh * 3 + kw) * OFFC];
#pragma unroll
                for (int co = 0; co < OFFC; co++)
                    acc[co] = fmaf(v, wr[co], acc[co]);
            }
        }
    }

    float* ob = g_offset + (size_t)b * OFFC * HW;
#pragma unroll
    for (int co = 0; co < OFFC; co++) ob[co * HW + hw] = acc[co];
}

// ---------------------------------------------------------------------------
// Kernel 2: deformable conv. One thread = one pixel, all 64 output channels
// accumulated in registers. q (kernel tap) is the OUTER loop so the bilinear
// indices/weights live only for one q at a time; channel loop inside reuses
// them. Weights transposed in dynamic smem: ws[(c*9+q)*64 + o] -> inner
// o-loop is contiguous float4 broadcast LDS feeding a 64-FFMA block.
// ---------------------------------------------------------------------------
__global__ __launch_bounds__(256, 1)
void deform_conv_kernel(const float* __restrict__ x,
                        const float* __restrict__ w,     // [64][64*9]
                        const float* __restrict__ bias,  // [64]
                        float* __restrict__ out)
{
    extern __shared__ float ws[];  // [576][64] = 147456 B
    const int tid = threadIdx.x;
    for (int i = tid; i < CIN * K2 * COUT; i += 256) {
        int cq = i >> 6, o = i & 63;
        ws[i] = w[o * (CIN * K2) + cq];
    }
    __syncthreads();

    const int pix = blockIdx.x * 256 + tid;
    const int b   = pix >> 14;
    const int hw  = pix & (HW - 1);
    const int ho  = hw >> 7;
    const int wo  = hw & (WW - 1);

    const float* xb   = x + (size_t)b * CIN * HW;
    const float* offb = g_offset + (size_t)b * OFFC * HW;

    float acc[COUT];
#pragma unroll
    for (int o = 0; o < COUT; o++) acc[o] = bias[o];

#pragma unroll 1
    for (int q = 0; q < K2; q++) {
        float dy = offb[(2 * q + 0) * HW + hw];
        float dx = offb[(2 * q + 1) * HW + hw];
        int kh = q / 3, kw = q - kh * 3;

        float py = (float)(ho - 1 + kh) + dy;
        float px = (float)(wo - 1 + kw) + dx;
        float y0f = floorf(py), x0f = floorf(px);
        int y0 = (int)y0f, x0 = (int)x0f;
        int y1 = y0 + 1,   x1 = x0 + 1;
        float wy1 = py - y0f, wx1 = px - x0f;
        float wy0 = 1.0f - wy1, wx0 = 1.0f - wx1;

        bool vy0 = (unsigned)y0 < (unsigned)HH;
        bool vy1 = (unsigned)y1 < (unsigned)HH;
        bool vx0 = (unsigned)x0 < (unsigned)WW;
        bool vx1 = (unsigned)x1 < (unsigned)WW;

        int yc0 = min(max(y0, 0), HH - 1), yc1 = min(max(y1, 0), HH - 1);
        int xc0 = min(max(x0, 0), WW - 1), xc1 = min(max(x1, 0), WW - 1);

        float w00 = (vy0 && vx0) ? wy0 * wx0 : 0.0f;
        float w01 = (vy0 && vx1) ? wy0 * wx1 : 0.0f;
        float w10 = (vy1 && vx0) ? wy1 * wx0 : 0.0f;
        float w11 = (vy1 && vx1) ? wy1 * wx1 : 0.0f;

        int i00 = yc0 * WW + xc0, i01 = yc0 * WW + xc1;
        int i10 = yc1 * WW + xc0, i11 = yc1 * WW + xc1;

        const float* wq = ws + q * COUT;

#pragma unroll 2
        for (int c = 0; c < CIN; c++) {
            const float* xc = xb + c * HW;
            float s = w00 * __ldg(xc + i00) + w01 * __ldg(xc + i01)
                    + w10 * __ldg(xc + i10) + w11 * __ldg(xc + i11);
            const float* wr = wq + c * (K2 * COUT);
#pragma unroll
            for (int o = 0; o < COUT; o++)
                acc[o] = fmaf(s, wr[o], acc[o]);
        }
    }

    float* ob = out + (size_t)b * COUT * HW;
#pragma unroll
    for (int o = 0; o < COUT; o++) ob[o * HW + hw] = acc[o];
}

// ---------------------------------------------------------------------------
extern "C" void kernel_launch(void* const* d_in, const int* in_sizes, int n_in,
                              void* d_out, int out_size)
{
    const float* x     = (const float*)d_in[0];  // [4,64,128,128]
    const float* w_off = (const float*)d_in[1];  // [18,64,3,3]
    const float* b_off = (const float*)d_in[2];  // [18]
    const float* w_def = (const float*)d_in[3];  // [64,64,3,3]
    const float* b_def = (const float*)d_in[4];  // [64]
    float* out = (float*)d_out;                  // [4,64,128,128]

    const int smem2 = CIN * K2 * COUT * (int)sizeof(float);  // 147456
    cudaFuncSetAttribute(deform_conv_kernel,
                         cudaFuncAttributeMaxDynamicSharedMemorySize, smem2);

    offset_conv_kernel<<<(BN * HW) / 256, 256>>>(x, w_off, b_off);
    deform_conv_kernel<<<(BN * HW) / 256, 256, smem2>>>(x, w_def, b_def, out);
}

// round 7
// speedup vs baseline: 1.0790x; 1.0790x over previous
#include <cuda_runtime.h>

#define BN   4
#define CIN  64
#define COUT 64
#define HH   128
#define WW   128
#define HW   (HH * WW)
#define K2q  9
#define OFFC 18

// Intermediate offset field scratch (no cudaMalloc allowed).
__device__ float g_offset[BN * OFFC * HW];

typedef unsigned long long ull;

// ---- packed f32x2 helpers --------------------------------------------------
__device__ __forceinline__ ull fma2(ull a, ull b, ull c) {
    ull d;
    asm("fma.rn.f32x2 %0, %1, %2, %3;" : "=l"(d) : "l"(a), "l"(b), "l"(c));
    return d;
}
__device__ __forceinline__ ull packs(float s) {   // {s, s}
    ull r; unsigned u = __float_as_uint(s);
    asm("mov.b64 %0, {%1, %1};" : "=l"(r) : "r"(u));
    return r;
}
__device__ __forceinline__ ull packf(float lo, float hi) {
    ull r;
    asm("mov.b64 %0, {%1, %2};" : "=l"(r)
        : "r"(__float_as_uint(lo)), "r"(__float_as_uint(hi)));
    return r;
}
__device__ __forceinline__ void unpackf(ull v, float& lo, float& hi) {
    unsigned a, b;
    asm("mov.b64 {%0, %1}, %2;" : "=r"(a), "=r"(b) : "l"(v));
    lo = __uint_as_float(a); hi = __uint_as_float(b);
}

// ============================================================================
// Kernel 1: plain 3x3 conv 64 -> 18, pad 1. 16x16 pixel tile per CTA,
// 18x18 smem x-tile (halo 1, zero-fill = implicit pad), double buffered.
// 9 packed f32x2 accumulators (18 channels).
// ============================================================================
#define T1   16
#define TS1  18
#define TP1  19

__global__ __launch_bounds__(256)
void offset_conv_kernel(const float* __restrict__ x,
                        const float* __restrict__ w,     // [18][64][3][3]
                        const float* __restrict__ bias)  // [18]
{
    __shared__ __align__(16) float ws[CIN * K2q * OFFC];  // [cq][co] 41472 B
    __shared__ __align__(16) float tb[2][TS1 * TP1];

    const int tid = threadIdx.x;
    for (int i = tid; i < CIN * K2q * OFFC; i += 256) {
        int cq = i / OFFC, co = i - cq * OFFC;
        ws[i] = w[co * (CIN * K2q) + cq];
    }

    const int bx  = blockIdx.x;
    const int b   = bx >> 6;
    const int t   = bx & 63;
    const int ty0 = (t >> 3) * T1, tx0 = (t & 7) * T1;
    const int ry0 = ty0 - 1, cx0 = tx0 - 1;
    const int ty  = tid >> 4, tx = tid & 15;
    const int ho  = ty0 + ty, wo = tx0 + tx;
    const int hw  = ho * WW + wo;
    const float* xb = x + (size_t)b * CIN * HW;

    // initial tile (c = 0), zero-filled outside image
    for (int i = tid; i < TS1 * TS1; i += 256) {
        int r = i / TS1, cl = i - r * TS1;
        int gy = ry0 + r, gx = cx0 + cl;
        float v = 0.f;
        if ((unsigned)gy < (unsigned)HH && (unsigned)gx < (unsigned)WW)
            v = __ldg(xb + gy * WW + gx);
        tb[0][r * TP1 + cl] = v;
    }
    __syncthreads();

    ull acc[9];
#pragma unroll
    for (int j = 0; j < 9; j++) acc[j] = packf(bias[2 * j], bias[2 * j + 1]);

#pragma unroll 1
    for (int c = 0; c < CIN; c++) {
        // prefetch channel c+1 into registers
        float p0 = 0.f, p1 = 0.f;
        if (c < CIN - 1) {
            const float* xc = xb + (c + 1) * HW;
            {
                int i = tid, r = i / TS1, cl = i - r * TS1;
                int gy = ry0 + r, gx = cx0 + cl;
                if ((unsigned)gy < (unsigned)HH && (unsigned)gx < (unsigned)WW)
                    p0 = __ldg(xc + gy * WW + gx);
            }
            if (tid < TS1 * TS1 - 256) {
                int i = tid + 256, r = i / TS1, cl = i - r * TS1;
                int gy = ry0 + r, gx = cx0 + cl;
                if ((unsigned)gy < (unsigned)HH && (unsigned)gx < (unsigned)WW)
                    p1 = __ldg(xc + gy * WW + gx);
            }
        }

        const float* tc = tb[c & 1];
#pragma unroll
        for (int kh = 0; kh < 3; kh++) {
#pragma unroll
            for (int kw = 0; kw < 3; kw++) {
                float v = tc[(ty + kh) * TP1 + (tx + kw)];
                ull v2 = packs(v);
                const ull* wp = (const ull*)(ws + (c * K2q + kh * 3 + kw) * OFFC);
#pragma unroll
                for (int j = 0; j < 9; j++) acc[j] = fma2(v2, wp[j], acc[j]);
            }
        }

        if (c < CIN - 1) {
            float* nb = tb[(c + 1) & 1];
            { int i = tid, r = i / TS1, cl = i - r * TS1; nb[r * TP1 + cl] = p0; }
            if (tid < TS1 * TS1 - 256) {
                int i = tid + 256, r = i / TS1, cl = i - r * TS1;
                nb[r * TP1 + cl] = p1;
            }
        }
        __syncthreads();
    }

    float* ob = g_offset + (size_t)b * OFFC * HW;
#pragma unroll
    for (int j = 0; j < 9; j++) {
        float lo, hi; unpackf(acc[j], lo, hi);
        ob[(2 * j) * HW + hw]     = lo;
        ob[(2 * j + 1) * HW + hw] = hi;
    }
}

// ============================================================================
// Kernel 2: deformable conv. 16x16 pixel tile per CTA, 24x24 smem x-tile
// (halo 4) per channel, double buffered; bilinear taps precomputed per pixel;
// warp-uniform fast path (all taps in-tile -> pure LDS) with clamped-LDG
// fallback. 32 packed f32x2 output accumulators; weights transposed in smem.
// ============================================================================
#define T2   16
#define HALO 4
#define TS   24
#define TP   25

__global__ __launch_bounds__(256, 1)
void deform_conv_kernel(const float* __restrict__ x,
                        const float* __restrict__ w,     // [64][64*9]
                        const float* __restrict__ bias,  // [64]
                        float* __restrict__ out)
{
    extern __shared__ __align__(16) float smem[];
    float* ws  = smem;                       // [576][64] = 147456 B
    float* tbA = smem + CIN * K2q * COUT;    // 600 floats
    float* tbB = tbA + TS * TP;              // 600 floats

    const int tid = threadIdx.x;
    for (int i = tid; i < CIN * K2q * COUT; i += 256) {
        int cq = i >> 6, o = i & 63;
        ws[i] = w[o * (CIN * K2q) + cq];
    }

    const int bx  = blockIdx.x;
    const int b   = bx >> 6;
    const int t   = bx & 63;
    const int ty0 = (t >> 3) * T2, tx0 = (t & 7) * T2;
    const int ry0 = ty0 - HALO, cx0 = tx0 - HALO;
    const int ty  = tid >> 4, tx = tid & 15;
    const int ho  = ty0 + ty, wo = tx0 + tx;
    const int hw  = ho * WW + wo;

    const float* xb   = x + (size_t)b * CIN * HW;
    const float* offb = g_offset + (size_t)b * OFFC * HW;

    // ---- precompute 9 bilinear taps (weights + tile-local base index) ----
    float4 tw[9];
    int    tsi[9];
    bool   allin = true;
#pragma unroll
    for (int q = 0; q < 9; q++) {
        float dy = offb[(2 * q) * HW + hw];
        float dx = offb[(2 * q + 1) * HW + hw];
        int kh = q / 3, kw = q - kh * 3;
        float py = (float)(ho - 1 + kh) + dy;
        float px = (float)(wo - 1 + kw) + dx;
        float y0f = floorf(py), x0f = floorf(px);
        int y0 = (int)y0f, x0 = (int)x0f;
        float wy1 = py - y0f, wx1 = px - x0f;
        float wy0 = 1.f - wy1, wx0 = 1.f - wx1;
        bool vy0 = (unsigned)y0 < (unsigned)HH;
        bool vy1 = (unsigned)(y0 + 1) < (unsigned)HH;
        bool vx0 = (unsigned)x0 < (unsigned)WW;
        bool vx1 = (unsigned)(x0 + 1) < (unsigned)WW;
        tw[q].x = (vy0 && vx0) ? wy0 * wx0 : 0.f;
        tw[q].y = (vy0 && vx1) ? wy0 * wx1 : 0.f;
        tw[q].z = (vy1 && vx0) ? wy1 * wx0 : 0.f;
        tw[q].w = (vy1 && vx1) ? wy1 * wx1 : 0.f;
        int ly = y0 - ry0, lx = x0 - cx0;
        bool in = (ly >= 0) && (ly <= TS - 2) && (lx >= 0) && (lx <= TS - 2);
        tsi[q] = in ? (ly * TP + lx) : -1;
        allin &= in;
    }
    unsigned mask = __ballot_sync(0xffffffffu, allin);
    const bool warp_fast = (mask == 0xffffffffu);

    // ---- initial tile (c = 0) ----
    for (int i = tid; i < TS * TS; i += 256) {
        int r = i / TS, cl = i - r * TS;
        int gy = ry0 + r, gx = cx0 + cl;
        float v = 0.f;
        if ((unsigned)gy < (unsigned)HH && (unsigned)gx < (unsigned)WW)
            v = __ldg(xb + gy * WW + gx);
        tbA[r * TP + cl] = v;
    }
    __syncthreads();

    ull acc[32];
#pragma unroll
    for (int j = 0; j < 32; j++) acc[j] = packf(bias[2 * j], bias[2 * j + 1]);

#pragma unroll 1
    for (int c = 0; c < CIN; c++) {
        float* tcur = (c & 1) ? tbB : tbA;
        float* tnxt = (c & 1) ? tbA : tbB;

        // prefetch channel c+1 (registers first -> overlap with compute)
        float p0 = 0.f, p1 = 0.f, p2 = 0.f;
        if (c < CIN - 1) {
            const float* xc = xb + (c + 1) * HW;
            {
                int i = tid, r = i / TS, cl = i - r * TS;
                int gy = ry0 + r, gx = cx0 + cl;
                if ((unsigned)gy < (unsigned)HH && (unsigned)gx < (unsigned)WW)
                    p0 = __ldg(xc + gy * WW + gx);
            }
            {
                int i = tid + 256, r = i / TS, cl = i - r * TS;
                int gy = ry0 + r, gx = cx0 + cl;
                if ((unsigned)gy < (unsigned)HH && (unsigned)gx < (unsigned)WW)
                    p1 = __ldg(xc + gy * WW + gx);
            }
            if (tid < TS * TS - 512) {
                int i = tid + 512, r = i / TS, cl = i - r * TS;
                int gy = ry0 + r, gx = cx0 + cl;
                if ((unsigned)gy < (unsigned)HH && (unsigned)gx < (unsigned)WW)
                    p2 = __ldg(xc + gy * WW + gx);
            }
        }

        if (warp_fast) {
            // all taps resolved in-tile: pure LDS sampling
#pragma unroll
            for (int q = 0; q < 9; q++) {
                int si = tsi[q];
                float s = tw[q].x * tcur[si]          + tw[q].y * tcur[si + 1]
                        + tw[q].z * tcur[si + TP]     + tw[q].w * tcur[si + TP + 1];
                ull s2 = packs(s);
                const ulonglong2* wp =
                    (const ulonglong2*)(ws + (c * K2q + q) * COUT);
#pragma unroll
                for (int j = 0; j < 16; j++) {
                    ulonglong2 wv = wp[j];
                    acc[2 * j]     = fma2(s2, wv.x, acc[2 * j]);
                    acc[2 * j + 1] = fma2(s2, wv.y, acc[2 * j + 1]);
                }
            }
        } else {
            // general path: per-tap in-tile test, clamped global fallback
            const float* xc = xb + c * HW;
#pragma unroll
            for (int q = 0; q < 9; q++) {
                int si = tsi[q];
                float s;
                if (si >= 0) {
                    s = tw[q].x * tcur[si]          + tw[q].y * tcur[si + 1]
                      + tw[q].z * tcur[si + TP]     + tw[q].w * tcur[si + TP + 1];
                } else {
                    float dy = __ldg(offb + (2 * q) * HW + hw);
                    float dx = __ldg(offb + (2 * q + 1) * HW + hw);
                    int kh = q / 3, kw = q - kh * 3;
                    int y0 = (int)floorf((float)(ho - 1 + kh) + dy);
                    int x0 = (int)floorf((float)(wo - 1 + kw) + dx);
                    int yc0 = min(max(y0, 0), HH - 1);
                    int yc1 = min(max(y0 + 1, 0), HH - 1);
                    int xc0i = min(max(x0, 0), WW - 1);
                    int xc1i = min(max(x0 + 1, 0), WW - 1);
                    s = tw[q].x * __ldg(xc + yc0 * WW + xc0i)
                      + tw[q].y * __ldg(xc + yc0 * WW + xc1i)
                      + tw[q].z * __ldg(xc + yc1 * WW + xc0i)
                      + tw[q].w * __ldg(xc + yc1 * WW + xc1i);
                }
                ull s2 = packs(s);
                const ulonglong2* wp =
                    (const ulonglong2*)(ws + (c * K2q + q) * COUT);
#pragma unroll
                for (int j = 0; j < 16; j++) {
                    ulonglong2 wv = wp[j];
                    acc[2 * j]     = fma2(s2, wv.x, acc[2 * j]);
                    acc[2 * j + 1] = fma2(s2, wv.y, acc[2 * j + 1]);
                }
            }
        }

        if (c < CIN - 1) {
            { int i = tid, r = i / TS, cl = i - r * TS; tnxt[r * TP + cl] = p0; }
            { int i = tid + 256, r = i / TS, cl = i - r * TS; tnxt[r * TP + cl] = p1; }
            if (tid < TS * TS - 512) {
                int i = tid + 512, r = i / TS, cl = i - r * TS;
                tnxt[r * TP + cl] = p2;
            }
        }
        __syncthreads();
    }

    float* ob = out + (size_t)b * COUT * HW;
#pragma unroll
    for (int j = 0; j < 32; j++) {
        float lo, hi; unpackf(acc[j], lo, hi);
        ob[(2 * j) * HW + hw]     = lo;
        ob[(2 * j + 1) * HW + hw] = hi;
    }
}

// ---------------------------------------------------------------------------
extern "C" void kernel_launch(void* const* d_in, const int* in_sizes, int n_in,
                              void* d_out, int out_size)
{
    const float* x     = (const float*)d_in[0];  // [4,64,128,128]
    const float* w_off = (const float*)d_in[1];  // [18,64,3,3]
    const float* b_off = (const float*)d_in[2];  // [18]
    const float* w_def = (const float*)d_in[3];  // [64,64,3,3]
    const float* b_def = (const float*)d_in[4];  // [64]
    float* out = (float*)d_out;                  // [4,64,128,128]

    const int smem2 = (CIN * K2q * COUT + 2 * TS * TP) * (int)sizeof(float);
    cudaFuncSetAttribute(deform_conv_kernel,
                         cudaFuncAttributeMaxDynamicSharedMemorySize, smem2);

    offset_conv_kernel<<<BN * 64, 256>>>(x, w_off, b_off);
    deform_conv_kernel<<<BN * 64, 256, smem2>>>(x, w_def, b_def, out);
}

// round 9
// speedup vs baseline: 1.0810x; 1.0018x over previous
#include <cuda_runtime.h>

#define BN   4
#define CIN  64
#define COUT 64
#define HH   128
#define WW   128
#define HW   (HH * WW)
#define K2q  9
#define OFFC 18

// Intermediate offset field scratch (no cudaMalloc allowed).
__device__ float g_offset[BN * OFFC * HW];

typedef unsigned long long ull;

// ---- packed f32x2 helpers --------------------------------------------------
__device__ __forceinline__ ull fma2(ull a, ull b, ull c) {
    ull d;
    asm("fma.rn.f32x2 %0, %1, %2, %3;" : "=l"(d) : "l"(a), "l"(b), "l"(c));
    return d;
}
__device__ __forceinline__ ull packs(float s) {   // {s, s}
    ull r; unsigned u = __float_as_uint(s);
    asm("mov.b64 %0, {%1, %1};" : "=l"(r) : "r"(u));
    return r;
}
__device__ __forceinline__ ull packf(float lo, float hi) {
    ull r;
    asm("mov.b64 %0, {%1, %2};" : "=l"(r)
        : "r"(__float_as_uint(lo)), "r"(__float_as_uint(hi)));
    return r;
}
__device__ __forceinline__ void unpackf(ull v, float& lo, float& hi) {
    unsigned a, b;
    asm("mov.b64 {%0, %1}, %2;" : "=r"(a), "=r"(b) : "l"(v));
    lo = __uint_as_float(a); hi = __uint_as_float(b);
}

// ============================================================================
// Kernel 1: plain 3x3 conv 64 -> 18, pad 1. 16x16 pixel tile per CTA,
// 18x18 smem x-tile (halo 1, zero-fill = implicit pad), double buffered.
// 9 packed f32x2 accumulators (18 channels).
// ============================================================================
#define T1   16
#define TS1  18
#define TP1  19

__global__ __launch_bounds__(256)
void offset_conv_kernel(const float* __restrict__ x,
                        const float* __restrict__ w,     // [18][64][3][3]
                        const float* __restrict__ bias)  // [18]
{
    __shared__ __align__(16) float ws[CIN * K2q * OFFC];  // [cq][co] 41472 B
    __shared__ __align__(16) float tb[2][TS1 * TP1];

    const int tid = threadIdx.x;
    for (int i = tid; i < CIN * K2q * OFFC; i += 256) {
        int cq = i / OFFC, co = i - cq * OFFC;
        ws[i] = w[co * (CIN * K2q) + cq];
    }

    const int bx  = blockIdx.x;
    const int b   = bx >> 6;
    const int t   = bx & 63;
    const int ty0 = (t >> 3) * T1, tx0 = (t & 7) * T1;
    const int ry0 = ty0 - 1, cx0 = tx0 - 1;
    const int ty  = tid >> 4, tx = tid & 15;
    const int ho  = ty0 + ty, wo = tx0 + tx;
    const int hw  = ho * WW + wo;
    const float* xb = x + (size_t)b * CIN * HW;

    // initial tile (c = 0), zero-filled outside image
    for (int i = tid; i < TS1 * TS1; i += 256) {
        int r = i / TS1, cl = i - r * TS1;
        int gy = ry0 + r, gx = cx0 + cl;
        float v = 0.f;
        if ((unsigned)gy < (unsigned)HH && (unsigned)gx < (unsigned)WW)
            v = __ldg(xb + gy * WW + gx);
        tb[0][r * TP1 + cl] = v;
    }
    __syncthreads();

    ull acc[9];
#pragma unroll
    for (int j = 0; j < 9; j++) acc[j] = packf(bias[2 * j], bias[2 * j + 1]);

#pragma unroll 1
    for (int c = 0; c < CIN; c++) {
        // prefetch channel c+1 into registers
        float p0 = 0.f, p1 = 0.f;
        if (c < CIN - 1) {
            const float* xc = xb + (c + 1) * HW;
            {
                int i = tid, r = i / TS1, cl = i - r * TS1;
                int gy = ry0 + r, gx = cx0 + cl;
                if ((unsigned)gy < (unsigned)HH && (unsigned)gx < (unsigned)WW)
                    p0 = __ldg(xc + gy * WW + gx);
            }
            if (tid < TS1 * TS1 - 256) {
                int i = tid + 256, r = i / TS1, cl = i - r * TS1;
                int gy = ry0 + r, gx = cx0 + cl;
                if ((unsigned)gy < (unsigned)HH && (unsigned)gx < (unsigned)WW)
                    p1 = __ldg(xc + gy * WW + gx);
            }
        }

        const float* tc = tb[c & 1];
#pragma unroll
        for (int kh = 0; kh < 3; kh++) {
#pragma unroll
            for (int kw = 0; kw < 3; kw++) {
                float v = tc[(ty + kh) * TP1 + (tx + kw)];
                ull v2 = packs(v);
                const ull* wp = (const ull*)(ws + (c * K2q + kh * 3 + kw) * OFFC);
#pragma unroll
                for (int j = 0; j < 9; j++) acc[j] = fma2(v2, wp[j], acc[j]);
            }
        }

        if (c < CIN - 1) {
            float* nb = tb[(c + 1) & 1];
            { int i = tid, r = i / TS1, cl = i - r * TS1; nb[r * TP1 + cl] = p0; }
            if (tid < TS1 * TS1 - 256) {
                int i = tid + 256, r = i / TS1, cl = i - r * TS1;
                nb[r * TP1 + cl] = p1;
            }
        }
        __syncthreads();
    }

    float* ob = g_offset + (size_t)b * OFFC * HW;
#pragma unroll
    for (int j = 0; j < 9; j++) {
        float lo, hi; unpackf(acc[j], lo, hi);
        ob[(2 * j) * HW + hw]     = lo;
        ob[(2 * j + 1) * HW + hw] = hi;
    }
}

// ============================================================================
// Kernel 2: deformable conv. 16x16 pixel tile per CTA, 24x24 smem x-tile
// (halo 4) per channel, double buffered; bilinear taps precomputed per pixel;
// warp-uniform fast path (all taps in-tile -> pure LDS) with clamped-LDG
// fallback. 32 packed f32x2 output accumulators; weights transposed in smem.
// ============================================================================
#define T2   16
#define HALO 4
#define TS   24
#define TP   25

__global__ __launch_bounds__(256, 1)
void deform_conv_kernel(const float* __restrict__ x,
                        const float* __restrict__ w,     // [64][64*9]
                        const float* __restrict__ bias,  // [64]
                        float* __restrict__ out)
{
    extern __shared__ __align__(16) float smem[];
    float* ws  = smem;                       // [576][64] = 147456 B
    float* tbA = smem + CIN * K2q * COUT;    // 600 floats
    float* tbB = tbA + TS * TP;              // 600 floats

    const int tid = threadIdx.x;
    for (int i = tid; i < CIN * K2q * COUT; i += 256) {
        int cq = i >> 6, o = i & 63;
        ws[i] = w[o * (CIN * K2q) + cq];
    }

    const int bx  = blockIdx.x;
    const int b   = bx >> 6;
    const int t   = bx & 63;
    const int ty0 = (t >> 3) * T2, tx0 = (t & 7) * T2;
    const int ry0 = ty0 - HALO, cx0 = tx0 - HALO;
    const int ty  = tid >> 4, tx = tid & 15;
    const int ho  = ty0 + ty, wo = tx0 + tx;
    const int hw  = ho * WW + wo;

    const float* xb   = x + (size_t)b * CIN * HW;
    const float* offb = g_offset + (size_t)b * OFFC * HW;

    // ---- precompute 9 bilinear taps (weights + tile-local base index) ----
    float4 tw[9];
    int    tsi[9];
    bool   allin = true;
#pragma unroll
    for (int q = 0; q < 9; q++) {
        float dy = offb[(2 * q) * HW + hw];
        float dx = offb[(2 * q + 1) * HW + hw];
        int kh = q / 3, kw = q - kh * 3;
        float py = (float)(ho - 1 + kh) + dy;
        float px = (float)(wo - 1 + kw) + dx;
        float y0f = floorf(py), x0f = floorf(px);
        int y0 = (int)y0f, x0 = (int)x0f;
        float wy1 = py - y0f, wx1 = px - x0f;
        float wy0 = 1.f - wy1, wx0 = 1.f - wx1;
        bool vy0 = (unsigned)y0 < (unsigned)HH;
        bool vy1 = (unsigned)(y0 + 1) < (unsigned)HH;
        bool vx0 = (unsigned)x0 < (unsigned)WW;
        bool vx1 = (unsigned)(x0 + 1) < (unsigned)WW;
        tw[q].x = (vy0 && vx0) ? wy0 * wx0 : 0.f;
        tw[q].y = (vy0 && vx1) ? wy0 * wx1 : 0.f;
        tw[q].z = (vy1 && vx0) ? wy1 * wx0 : 0.f;
        tw[q].w = (vy1 && vx1) ? wy1 * wx1 : 0.f;
        int ly = y0 - ry0, lx = x0 - cx0;
        bool in = (ly >= 0) && (ly <= TS - 2) && (lx >= 0) && (lx <= TS - 2);
        tsi[q] = in ? (ly * TP + lx) : -1;
        allin &= in;
    }
    unsigned mask = __ballot_sync(0xffffffffu, allin);
    const bool warp_fast = (mask == 0xffffffffu);

    // ---- initial tile (c = 0) ----
    for (int i = tid; i < TS * TS; i += 256) {
        int r = i / TS, cl = i - r * TS;
        int gy = ry0 + r, gx = cx0 + cl;
        float v = 0.f;
        if ((unsigned)gy < (unsigned)HH && (unsigned)gx < (unsigned)WW)
            v = __ldg(xb + gy * WW + gx);
        tbA[r * TP + cl] = v;
    }
    __syncthreads();

    ull acc[32];
#pragma unroll
    for (int j = 0; j < 32; j++) acc[j] = packf(bias[2 * j], bias[2 * j + 1]);

#pragma unroll 1
    for (int c = 0; c < CIN; c++) {
        float* tcur = (c & 1) ? tbB : tbA;
        float* tnxt = (c & 1) ? tbA : tbB;

        // prefetch channel c+1 (registers first -> overlap with compute)
        float p0 = 0.f, p1 = 0.f, p2 = 0.f;
        if (c < CIN - 1) {
            const float* xc = xb + (c + 1) * HW;
            {
                int i = tid, r = i / TS, cl = i - r * TS;
                int gy = ry0 + r, gx = cx0 + cl;
                if ((unsigned)gy < (unsigned)HH && (unsigned)gx < (unsigned)WW)
                    p0 = __ldg(xc + gy * WW + gx);
            }
            {
                int i = tid + 256, r = i / TS, cl = i - r * TS;
                int gy = ry0 + r, gx = cx0 + cl;
                if ((unsigned)gy < (unsigned)HH && (unsigned)gx < (unsigned)WW)
                    p1 = __ldg(xc + gy * WW + gx);
            }
            if (tid < TS * TS - 512) {
                int i = tid + 512, r = i / TS, cl = i - r * TS;
                int gy = ry0 + r, gx = cx0 + cl;
                if ((unsigned)gy < (unsigned)HH && (unsigned)gx < (unsigned)WW)
                    p2 = __ldg(xc + gy * WW + gx);
            }
        }

        if (warp_fast) {
            // all taps resolved in-tile: pure LDS sampling
#pragma unroll
            for (int q = 0; q < 9; q++) {
                int si = tsi[q];
                float s = tw[q].x * tcur[si]          + tw[q].y * tcur[si + 1]
                        + tw[q].z * tcur[si + TP]     + tw[q].w * tcur[si + TP + 1];
                ull s2 = packs(s);
                const ulonglong2* wp =
                    (const ulonglong2*)(ws + (c * K2q + q) * COUT);
#pragma unroll
                for (int j = 0; j < 16; j++) {
                    ulonglong2 wv = wp[j];
                    acc[2 * j]     = fma2(s2, wv.x, acc[2 * j]);
                    acc[2 * j + 1] = fma2(s2, wv.y, acc[2 * j + 1]);
                }
            }
        } else {
            // general path: per-tap in-tile test, clamped global fallback
            const float* xc = xb + c * HW;
#pragma unroll
            for (int q = 0; q < 9; q++) {
                int si = tsi[q];
                float s;
                if (si >= 0) {
                    s = tw[q].x * tcur[si]          + tw[q].y * tcur[si + 1]
                      + tw[q].z * tcur[si + TP]     + tw[q].w * tcur[si + TP + 1];
                } else {
                    float dy = __ldg(offb + (2 * q) * HW + hw);
                    float dx = __ldg(offb + (2 * q + 1) * HW + hw);
                    int kh = q / 3, kw = q - kh * 3;
                    int y0 = (int)floorf((float)(ho - 1 + kh) + dy);
                    int x0 = (int)floorf((float)(wo - 1 + kw) + dx);
                    int yc0 = min(max(y0, 0), HH - 1);
                    int yc1 = min(max(y0 + 1, 0), HH - 1);
                    int xc0i = min(max(x0, 0), WW - 1);
                    int xc1i = min(max(x0 + 1, 0), WW - 1);
                    s = tw[q].x * __ldg(xc + yc0 * WW + xc0i)
                      + tw[q].y * __ldg(xc + yc0 * WW + xc1i)
                      + tw[q].z * __ldg(xc + yc1 * WW + xc0i)
                      + tw[q].w * __ldg(xc + yc1 * WW + xc1i);
                }
                ull s2 = packs(s);
                const ulonglong2* wp =
                    (const ulonglong2*)(ws + (c * K2q + q) * COUT);
#pragma unroll
                for (int j = 0; j < 16; j++) {
                    ulonglong2 wv = wp[j];
                    acc[2 * j]     = fma2(s2, wv.x, acc[2 * j]);
                    acc[2 * j + 1] = fma2(s2, wv.y, acc[2 * j + 1]);
                }
            }
        }

        if (c < CIN - 1) {
            { int i = tid, r = i / TS, cl = i - r * TS; tnxt[r * TP + cl] = p0; }
            { int i = tid + 256, r = i / TS, cl = i - r * TS; tnxt[r * TP + cl] = p1; }
            if (tid < TS * TS - 512) {
                int i = tid + 512, r = i / TS, cl = i - r * TS;
                tnxt[r * TP + cl] = p2;
            }
        }
        __syncthreads();
    }

    float* ob = out + (size_t)b * COUT * HW;
#pragma unroll
    for (int j = 0; j < 32; j++) {
        float lo, hi; unpackf(acc[j], lo, hi);
        ob[(2 * j) * HW + hw]     = lo;
        ob[(2 * j + 1) * HW + hw] = hi;
    }
}

// ---------------------------------------------------------------------------
extern "C" void kernel_launch(void* const* d_in, const int* in_sizes, int n_in,
                              void* d_out, int out_size)
{
    const float* x     = (const float*)d_in[0];  // [4,64,128,128]
    const float* w_off = (const float*)d_in[1];  // [18,64,3,3]
    const float* b_off = (const float*)d_in[2];  // [18]
    const float* w_def = (const float*)d_in[3];  // [64,64,3,3]
    const float* b_def = (const float*)d_in[4];  // [64]
    float* out = (float*)d_out;                  // [4,64,128,128]

    const int smem2 = (CIN * K2q * COUT + 2 * TS * TP) * (int)sizeof(float);
    cudaFuncSetAttribute(deform_conv_kernel,
                         cudaFuncAttributeMaxDynamicSharedMemorySize, smem2);

    offset_conv_kernel<<<BN * 64, 256>>>(x, w_off, b_off);
    deform_conv_kernel<<<BN * 64, 256, smem2>>>(x, w_def, b_def, out);
}

// round 10
// speedup vs baseline: 1.0849x; 1.0036x over previous
#include <cuda_runtime.h>

#define BN   4
#define CIN  64
#define COUT 64
#define HH   128
#define WW   128
#define HW   (HH * WW)
#define K2q  9
#define OFFC 18

// Intermediate offset field scratch (no cudaMalloc allowed).
__device__ float g_offset[BN * OFFC * HW];

typedef unsigned long long ull;

// ---- packed f32x2 helpers --------------------------------------------------
__device__ __forceinline__ ull fma2(ull a, ull b, ull c) {
    ull d;
    asm("fma.rn.f32x2 %0, %1, %2, %3;" : "=l"(d) : "l"(a), "l"(b), "l"(c));
    return d;
}
__device__ __forceinline__ ull packs(float s) {   // {s, s}
    ull r; unsigned u = __float_as_uint(s);
    asm("mov.b64 %0, {%1, %1};" : "=l"(r) : "r"(u));
    return r;
}
__device__ __forceinline__ ull packf(float lo, float hi) {
    ull r;
    asm("mov.b64 %0, {%1, %2};" : "=l"(r)
        : "r"(__float_as_uint(lo)), "r"(__float_as_uint(hi)));
    return r;
}
__device__ __forceinline__ void unpackf(ull v, float& lo, float& hi) {
    unsigned a, b;
    asm("mov.b64 {%0, %1}, %2;" : "=r"(a), "=r"(b) : "l"(v));
    lo = __uint_as_float(a); hi = __uint_as_float(b);
}

// ============================================================================
// Kernel 1: plain 3x3 conv 64 -> 18, pad 1. 16x16 pixel tile per CTA,
// 18x18 smem x-tile (halo 1, zero-fill = implicit pad), double buffered.
// 9 packed f32x2 accumulators (18 channels).
// ============================================================================
#define T1   16
#define TS1  18
#define TP1  19

__global__ __launch_bounds__(256)
void offset_conv_kernel(const float* __restrict__ x,
                        const float* __restrict__ w,     // [18][64][3][3]
                        const float* __restrict__ bias)  // [18]
{
    __shared__ __align__(16) float ws[CIN * K2q * OFFC];  // [cq][co] 41472 B
    __shared__ __align__(16) float tb[2][TS1 * TP1];

    const int tid = threadIdx.x;
    for (int i = tid; i < CIN * K2q * OFFC; i += 256) {
        int cq = i / OFFC, co = i - cq * OFFC;
        ws[i] = w[co * (CIN * K2q) + cq];
    }

    const int bx  = blockIdx.x;
    const int b   = bx >> 6;
    const int t   = bx & 63;
    const int ty0 = (t >> 3) * T1, tx0 = (t & 7) * T1;
    const int ry0 = ty0 - 1, cx0 = tx0 - 1;
    const int ty  = tid >> 4, tx = tid & 15;
    const int ho  = ty0 + ty, wo = tx0 + tx;
    const int hw  = ho * WW + wo;
    const float* xb = x + (size_t)b * CIN * HW;

    // initial tile (c = 0), zero-filled outside image
    for (int i = tid; i < TS1 * TS1; i += 256) {
        int r = i / TS1, cl = i - r * TS1;
        int gy = ry0 + r, gx = cx0 + cl;
        float v = 0.f;
        if ((unsigned)gy < (unsigned)HH && (unsigned)gx < (unsigned)WW)
            v = __ldg(xb + gy * WW + gx);
        tb[0][r * TP1 + cl] = v;
    }
    __syncthreads();

    ull acc[9];
#pragma unroll
    for (int j = 0; j < 9; j++) acc[j] = packf(bias[2 * j], bias[2 * j + 1]);

#pragma unroll 1
    for (int c = 0; c < CIN; c++) {
        // prefetch channel c+1 into registers
        float p0 = 0.f, p1 = 0.f;
        if (c < CIN - 1) {
            const float* xc = xb + (c + 1) * HW;
            {
                int i = tid, r = i / TS1, cl = i - r * TS1;
                int gy = ry0 + r, gx = cx0 + cl;
                if ((unsigned)gy < (unsigned)HH && (unsigned)gx < (unsigned)WW)
                    p0 = __ldg(xc + gy * WW + gx);
            }
            if (tid < TS1 * TS1 - 256) {
                int i = tid + 256, r = i / TS1, cl = i - r * TS1;
                int gy = ry0 + r, gx = cx0 + cl;
                if ((unsigned)gy < (unsigned)HH && (unsigned)gx < (unsigned)WW)
                    p1 = __ldg(xc + gy * WW + gx);
            }
        }

        const float* tc = tb[c & 1];
#pragma unroll
        for (int kh = 0; kh < 3; kh++) {
#pragma unroll
            for (int kw = 0; kw < 3; kw++) {
                float v = tc[(ty + kh) * TP1 + (tx + kw)];
                ull v2 = packs(v);
                const ull* wp = (const ull*)(ws + (c * K2q + kh * 3 + kw) * OFFC);
#pragma unroll
                for (int j = 0; j < 9; j++) acc[j] = fma2(v2, wp[j], acc[j]);
            }
        }

        if (c < CIN - 1) {
            float* nb = tb[(c + 1) & 1];
            { int i = tid, r = i / TS1, cl = i - r * TS1; nb[r * TP1 + cl] = p0; }
            if (tid < TS1 * TS1 - 256) {
                int i = tid + 256, r = i / TS1, cl = i - r * TS1;
                nb[r * TP1 + cl] = p1;
            }
        }
        __syncthreads();
    }

    float* ob = g_offset + (size_t)b * OFFC * HW;
#pragma unroll
    for (int j = 0; j < 9; j++) {
        float lo, hi; unpackf(acc[j], lo, hi);
        ob[(2 * j) * HW + hw]     = lo;
        ob[(2 * j + 1) * HW + hw] = hi;
    }
}

// ============================================================================
// Kernel 2: deformable conv. 16x16 pixel tile per CTA, 24x24 smem x-tile
// (halo 4) per channel, double buffered; bilinear taps precomputed per pixel;
// warp-uniform fast path (all taps in-tile -> pure LDS) with clamped-LDG
// fallback. 32 packed f32x2 output accumulators; weights transposed in smem.
// ============================================================================
#define T2   16
#define HALO 4
#define TS   24
#define TP   25

__global__ __launch_bounds__(256, 1)
void deform_conv_kernel(const float* __restrict__ x,
                        const float* __restrict__ w,     // [64][64*9]
                        const float* __restrict__ bias,  // [64]
                        float* __restrict__ out)
{
    extern __shared__ __align__(16) float smem[];
    float* ws  = smem;                       // [576][64] = 147456 B
    float* tbA = smem + CIN * K2q * COUT;    // 600 floats
    float* tbB = tbA + TS * TP;              // 600 floats

    const int tid = threadIdx.x;
    for (int i = tid; i < CIN * K2q * COUT; i += 256) {
        int cq = i >> 6, o = i & 63;
        ws[i] = w[o * (CIN * K2q) + cq];
    }

    const int bx  = blockIdx.x;
    const int b   = bx >> 6;
    const int t   = bx & 63;
    const int ty0 = (t >> 3) * T2, tx0 = (t & 7) * T2;
    const int ry0 = ty0 - HALO, cx0 = tx0 - HALO;
    const int ty  = tid >> 4, tx = tid & 15;
    const int ho  = ty0 + ty, wo = tx0 + tx;
    const int hw  = ho * WW + wo;

    const float* xb   = x + (size_t)b * CIN * HW;
    const float* offb = g_offset + (size_t)b * OFFC * HW;

    // ---- precompute 9 bilinear taps (weights + tile-local base index) ----
    float4 tw[9];
    int    tsi[9];
    bool   allin = true;
#pragma unroll
    for (int q = 0; q < 9; q++) {
        float dy = offb[(2 * q) * HW + hw];
        float dx = offb[(2 * q + 1) * HW + hw];
        int kh = q / 3, kw = q - kh * 3;
        float py = (float)(ho - 1 + kh) + dy;
        float px = (float)(wo - 1 + kw) + dx;
        float y0f = floorf(py), x0f = floorf(px);
        int y0 = (int)y0f, x0 = (int)x0f;
        float wy1 = py - y0f, wx1 = px - x0f;
        float wy0 = 1.f - wy1, wx0 = 1.f - wx1;
        bool vy0 = (unsigned)y0 < (unsigned)HH;
        bool vy1 = (unsigned)(y0 + 1) < (unsigned)HH;
        bool vx0 = (unsigned)x0 < (unsigned)WW;
        bool vx1 = (unsigned)(x0 + 1) < (unsigned)WW;
        tw[q].x = (vy0 && vx0) ? wy0 * wx0 : 0.f;
        tw[q].y = (vy0 && vx1) ? wy0 * wx1 : 0.f;
        tw[q].z = (vy1 && vx0) ? wy1 * wx0 : 0.f;
        tw[q].w = (vy1 && vx1) ? wy1 * wx1 : 0.f;
        int ly = y0 - ry0, lx = x0 - cx0;
        bool in = (ly >= 0) && (ly <= TS - 2) && (lx >= 0) && (lx <= TS - 2);
        tsi[q] = in ? (ly * TP + lx) : -1;
        allin &= in;
    }
    unsigned mask = __ballot_sync(0xffffffffu, allin);
    const bool warp_fast = (mask == 0xffffffffu);

    // ---- initial tile (c = 0) ----
    for (int i = tid; i < TS * TS; i += 256) {
        int r = i / TS, cl = i - r * TS;
        int gy = ry0 + r, gx = cx0 + cl;
        float v = 0.f;
        if ((unsigned)gy < (unsigned)HH && (unsigned)gx < (unsigned)WW)
            v = __ldg(xb + gy * WW + gx);
        tbA[r * TP + cl] = v;
    }
    __syncthreads();

    ull acc[32];
#pragma unroll
    for (int j = 0; j < 32; j++) acc[j] = packf(bias[2 * j], bias[2 * j + 1]);

#pragma unroll 1
    for (int c = 0; c < CIN; c++) {
        float* tcur = (c & 1) ? tbB : tbA;
        float* tnxt = (c & 1) ? tbA : tbB;

        // prefetch channel c+1 (registers first -> overlap with compute)
        float p0 = 0.f, p1 = 0.f, p2 = 0.f;
        if (c < CIN - 1) {
            const float* xc = xb + (c + 1) * HW;
            {
                int i = tid, r = i / TS, cl = i - r * TS;
                int gy = ry0 + r, gx = cx0 + cl;
                if ((unsigned)gy < (unsigned)HH && (unsigned)gx < (unsigned)WW)
                    p0 = __ldg(xc + gy * WW + gx);
            }
            {
                int i = tid + 256, r = i / TS, cl = i - r * TS;
                int gy = ry0 + r, gx = cx0 + cl;
                if ((unsigned)gy < (unsigned)HH && (unsigned)gx < (unsigned)WW)
                    p1 = __ldg(xc + gy * WW + gx);
            }
            if (tid < TS * TS - 512) {
                int i = tid + 512, r = i / TS, cl = i - r * TS;
                int gy = ry0 + r, gx = cx0 + cl;
                if ((unsigned)gy < (unsigned)HH && (unsigned)gx < (unsigned)WW)
                    p2 = __ldg(xc + gy * WW + gx);
            }
        }

        if (warp_fast) {
            // all taps resolved in-tile: pure LDS sampling
#pragma unroll
            for (int q = 0; q < 9; q++) {
                int si = tsi[q];
                float s = tw[q].x * tcur[si]          + tw[q].y * tcur[si + 1]
                        + tw[q].z * tcur[si + TP]     + tw[q].w * tcur[si + TP + 1];
                ull s2 = packs(s);
                const ulonglong2* wp =
                    (const ulonglong2*)(ws + (c * K2q + q) * COUT);
#pragma unroll
                for (int j = 0; j < 16; j++) {
                    ulonglong2 wv = wp[j];
                    acc[2 * j]     = fma2(s2, wv.x, acc[2 * j]);
                    acc[2 * j + 1] = fma2(s2, wv.y, acc[2 * j + 1]);
                }
            }
        } else {
            // general path: per-tap in-tile test, clamped global fallback
            const float* xc = xb + c * HW;
#pragma unroll
            for (int q = 0; q < 9; q++) {
                int si = tsi[q];
                float s;
                if (si >= 0) {
                    s = tw[q].x * tcur[si]          + tw[q].y * tcur[si + 1]
                      + tw[q].z * tcur[si + TP]     + tw[q].w * tcur[si + TP + 1];
                } else {
                    float dy = __ldg(offb + (2 * q) * HW + hw);
                    float dx = __ldg(offb + (2 * q + 1) * HW + hw);
                    int kh = q / 3, kw = q - kh * 3;
                    int y0 = (int)floorf((float)(ho - 1 + kh) + dy);
                    int x0 = (int)floorf((float)(wo - 1 + kw) + dx);
                    int yc0 = min(max(y0, 0), HH - 1);
                    int yc1 = min(max(y0 + 1, 0), HH - 1);
                    int xc0i = min(max(x0, 0), WW - 1);
                    int xc1i = min(max(x0 + 1, 0), WW - 1);
                    s = tw[q].x * __ldg(xc + yc0 * WW + xc0i)
                      + tw[q].y * __ldg(xc + yc0 * WW + xc1i)
                      + tw[q].z * __ldg(xc + yc1 * WW + xc0i)
                      + tw[q].w * __ldg(xc + yc1 * WW + xc1i);
                }
                ull s2 = packs(s);
                const ulonglong2* wp =
                    (const ulonglong2*)(ws + (c * K2q + q) * COUT);
#pragma unroll
                for (int j = 0; j < 16; j++) {
                    ulonglong2 wv = wp[j];
                    acc[2 * j]     = fma2(s2, wv.x, acc[2 * j]);
                    acc[2 * j + 1] = fma2(s2, wv.y, acc[2 * j + 1]);
                }
            }
        }

        if (c < CIN - 1) {
            { int i = tid, r = i / TS, cl = i - r * TS; tnxt[r * TP + cl] = p0; }
            { int i = tid + 256, r = i / TS, cl = i - r * TS; tnxt[r * TP + cl] = p1; }
            if (tid < TS * TS - 512) {
                int i = tid + 512, r = i / TS, cl = i - r * TS;
                tnxt[r * TP + cl] = p2;
            }
        }
        __syncthreads();
    }

    float* ob = out + (size_t)b * COUT * HW;
#pragma unroll
    for (int j = 0; j < 32; j++) {
        float lo, hi; unpackf(acc[j], lo, hi);
        ob[(2 * j) * HW + hw]     = lo;
        ob[(2 * j + 1) * HW + hw] = hi;
    }
}

// ---------------------------------------------------------------------------
extern "C" void kernel_launch(void* const* d_in, const int* in_sizes, int n_in,
                              void* d_out, int out_size)
{
    const float* x     = (const float*)d_in[0];  // [4,64,128,128]
    const float* w_off = (const float*)d_in[1];  // [18,64,3,3]
    const float* b_off = (const float*)d_in[2];  // [18]
    const float* w_def = (const float*)d_in[3];  // [64,64,3,3]
    const float* b_def = (const float*)d_in[4];  // [64]
    float* out = (float*)d_out;                  // [4,64,128,128]

    const int smem2 = (CIN * K2q * COUT + 2 * TS * TP) * (int)sizeof(float);
    cudaFuncSetAttribute(deform_conv_kernel,
                         cudaFuncAttributeMaxDynamicSharedMemorySize, smem2);

    offset_conv_kernel<<<BN * 64, 256>>>(x, w_off, b_off);
    deform_conv_kernel<<<BN * 64, 256, smem2>>>(x, w_def, b_def, out);
}